// round 9
// baseline (speedup 1.0000x reference)
#include <cuda_runtime.h>
#include <cuda_bf16.h>
#include <cstdint>

// Problem constants
#define SEQ  2048
#define HID  1024
#define NH   16
#define HD   64
#define QKVN (3 * HID)   // 3072

// Scratch (allocation-free rule: __device__ globals)
__device__ float g_qkv[SEQ * QKVN];        // [2048, 3072]  (tf32-rounded values)
__device__ float g_attn[SEQ * HID];        // [2048, 1024]  (tf32-rounded values)
__device__ float g_xr[SEQ * HID];          // x rounded to tf32
__device__ float g_war[HID * QKVN];        // w_attn rounded to tf32
__device__ float g_wpr[HID * HID];         // w_proj rounded to tf32

// ===========================================================================
// Helpers
// ===========================================================================
__device__ __forceinline__ uint32_t smem_u32(const void* p) {
    uint32_t a;
    asm("{ .reg .u64 t; cvta.to.shared.u64 t, %1; cvt.u32.u64 %0, t; }" : "=r"(a) : "l"(p));
    return a;
}
__device__ __forceinline__ uint32_t f2tf32(float v) {
    uint32_t r;
    asm("cvt.rna.tf32.f32 %0, %1;" : "=r"(r) : "f"(v));
    return r;
}
__device__ __forceinline__ float tf32v(float v) {
    return __uint_as_float(f2tf32(v));
}
__device__ __forceinline__ void mma_tf32(float d[4],
                                         uint32_t a0, uint32_t a1, uint32_t a2, uint32_t a3,
                                         uint32_t b0, uint32_t b1) {
    asm volatile(
        "mma.sync.aligned.m16n8k8.row.col.f32.tf32.tf32.f32 "
        "{%0,%1,%2,%3}, {%4,%5,%6,%7}, {%8,%9}, {%0,%1,%2,%3};"
        : "+f"(d[0]), "+f"(d[1]), "+f"(d[2]), "+f"(d[3])
        : "r"(a0), "r"(a1), "r"(a2), "r"(a3), "r"(b0), "r"(b1));
}
#define CP_ASYNC16(dst_u32, src_ptr) \
    asm volatile("cp.async.cg.shared.global [%0], [%1], 16;" :: "r"(dst_u32), "l"(src_ptr))
#define CP_COMMIT() asm volatile("cp.async.commit_group;" ::: "memory")
#define CP_WAIT1()  asm volatile("cp.async.wait_group 1;" ::: "memory")
#define CP_WAIT0()  asm volatile("cp.async.wait_group 0;" ::: "memory")

// ===========================================================================
// Elementwise tf32 rounding pass (run once per call on x / w_attn / w_proj)
// ===========================================================================
__global__ __launch_bounds__(256) void round_tf32(
    const float* __restrict__ in, float* __restrict__ out, int n4)
{
    int i = blockIdx.x * 256 + threadIdx.x;
    if (i < n4) {
        float4 v = *(const float4*)(in + i * 4);
        float4 w;
        w.x = tf32v(v.x); w.y = tf32v(v.y); w.z = tf32v(v.z); w.w = tf32v(v.w);
        *(float4*)(out + i * 4) = w;
    }
}

// ===========================================================================
// tf32 mma.sync GEMM: C[M,N] = A[M,K] @ B[K,N] + bias[N]   (B row-major)
// Inputs already tf32-rounded. 3-stage cp.async ring, ONE syncthreads/stage.
// CTA 128x128, BK=32, 256 threads (8 warps 2x4), warp 64x32.
// ===========================================================================
#define LDA 36
#define LDB 136
#define A_STAGE (128 * LDA)     // floats
#define B_STAGE (32 * LDB)
#define GEMM_SMEM (3 * (A_STAGE + B_STAGE) * 4)

__global__ __launch_bounds__(256)
void gemm_tf32(const float* __restrict__ A, const float* __restrict__ B,
               const float* __restrict__ bias, float* __restrict__ C,
               int M, int N, int K, int round_out)
{
    extern __shared__ float smem[];
    float* As = smem;                      // [3][A_STAGE]
    float* Bs = smem + 3 * A_STAGE;        // [3][B_STAGE]
    const uint32_t as_u32 = smem_u32(As);
    const uint32_t bs_u32 = smem_u32(Bs);

    const int tid  = threadIdx.x;
    const int wid  = tid >> 5;
    const int lane = tid & 31;
    const int g = lane >> 2;
    const int t = lane & 3;
    const int wy = wid >> 2;                // 0..1
    const int wx = wid & 3;                 // 0..3
    const int row0 = blockIdx.y * 128;
    const int col0 = blockIdx.x * 128;
    const int NS = K >> 5;

    const float* Ag = A + (size_t)row0 * K;
    const float* Bg = B + col0;

    auto copy_stage = [&](int s, int buf) {
        const int k0 = s * 32;
#pragma unroll
        for (int u = 0; u < 4; u++) {
            int idx = u * 256 + tid;
            int row = idx >> 3;
            int c4  = idx & 7;
            CP_ASYNC16(as_u32 + (buf * A_STAGE + row * LDA + c4 * 4) * 4,
                       Ag + (size_t)row * K + k0 + c4 * 4);
        }
#pragma unroll
        for (int u = 0; u < 4; u++) {
            int idx = u * 256 + tid;
            int row = idx >> 5;
            int c4  = idx & 31;
            CP_ASYNC16(bs_u32 + (buf * B_STAGE + row * LDB + c4 * 4) * 4,
                       Bg + (size_t)(k0 + row) * N + c4 * 4);
        }
    };

    float acc[4][4][4];
#pragma unroll
    for (int mt = 0; mt < 4; mt++)
#pragma unroll
        for (int nt = 0; nt < 4; nt++)
#pragma unroll
            for (int r = 0; r < 4; r++) acc[mt][nt][r] = 0.f;

    copy_stage(0, 0); CP_COMMIT();
    copy_stage(1, 1); CP_COMMIT();

    for (int s = 0; s < NS; s++) {
        if (s == NS - 1) { CP_WAIT0(); } else { CP_WAIT1(); }
        __syncthreads();   // stage s visible to all; all warps done with buf (s+2)%3
        if (s + 2 < NS) { copy_stage(s + 2, (s + 2) % 3); CP_COMMIT(); }

        const float* Ab = As + (s % 3) * A_STAGE;
        const float* Bb = Bs + (s % 3) * B_STAGE;

#pragma unroll
        for (int ks = 0; ks < 4; ks++) {
            const int kk = ks * 8;
            uint32_t af[4][4];
#pragma unroll
            for (int mt = 0; mt < 4; mt++) {
                const float* pa = Ab + (wy * 64 + mt * 16 + g) * LDA + kk + t;
                af[mt][0] = __float_as_uint(pa[0]);
                af[mt][1] = __float_as_uint(pa[8 * LDA]);
                af[mt][2] = __float_as_uint(pa[4]);
                af[mt][3] = __float_as_uint(pa[8 * LDA + 4]);
            }
            uint32_t bf[4][2];
#pragma unroll
            for (int nt = 0; nt < 4; nt++) {
                const float* pb = Bb + (kk + t) * LDB + wx * 32 + nt * 8 + g;
                bf[nt][0] = __float_as_uint(pb[0]);
                bf[nt][1] = __float_as_uint(pb[4 * LDB]);
            }
#pragma unroll
            for (int mt = 0; mt < 4; mt++)
#pragma unroll
                for (int nt = 0; nt < 4; nt++)
                    mma_tf32(acc[mt][nt], af[mt][0], af[mt][1], af[mt][2], af[mt][3],
                             bf[nt][0], bf[nt][1]);
        }
    }

#pragma unroll
    for (int mt = 0; mt < 4; mt++) {
        int m = row0 + wy * 64 + mt * 16 + g;
#pragma unroll
        for (int nt = 0; nt < 4; nt++) {
            int n = col0 + wx * 32 + nt * 8 + 2 * t;
            float2 o0, o1;
            o0.x = acc[mt][nt][0] + bias[n];
            o0.y = acc[mt][nt][1] + bias[n + 1];
            o1.x = acc[mt][nt][2] + bias[n];
            o1.y = acc[mt][nt][3] + bias[n + 1];
            if (round_out) {
                o0.x = tf32v(o0.x); o0.y = tf32v(o0.y);
                o1.x = tf32v(o1.x); o1.y = tf32v(o1.y);
            }
            *(float2*)(C + (size_t)m * N + n)       = o0;
            *(float2*)(C + (size_t)(m + 8) * N + n) = o1;
        }
    }
}

// ===========================================================================
// Flash attention, tf32 mma.sync, FRAGMENT-LAYOUT smem.
// CTA = (head, 64 q rows), 4 warps. Q persistent in registers.
// R0 (8448 floats): Q-stage [64][68] -> KF (B-frag layout) -> PF (A-frag, warp-private)
// R1 (8288 floats): VF (B-frag layout)
// KF[nt<16][ks<8][lane][slot]  off = nt*528 + ks*66 + lane*2 + slot
// VF[nt<8][ks<16][lane][slot]  off = nt*1034 + ks*64 + lane*2 + slot
// PF[wid][ks<16][lane][4]      off = wid*2048 + ks*128 + lane*4 + slot
// ===========================================================================
#define ALD 68
#define R0_FLOATS 8448
#define R1_FLOATS 8288
#define ATTN_FLOATS (R0_FLOATS + R1_FLOATS)
#define ATTN_BYTES  (ATTN_FLOATS * 4)

__global__ __launch_bounds__(128)
void attn_mma(const float* __restrict__ qkv, float* __restrict__ out)
{
    extern __shared__ float sm[];
    float* R0 = sm;                 // Qstage | KF | PF
    float* R1 = sm + R0_FLOATS;     // VF

    const int tid  = threadIdx.x;
    const int lane = tid & 31;
    const int wid  = tid >> 5;     // 0..3
    const int g = lane >> 2;
    const int t = lane & 3;
    const int h  = blockIdx.y;
    const int qb = (int)gridDim.x - 1 - (int)blockIdx.x;   // heavy CTAs first
    const int q0 = qb * 64;
    const int rowbase = wid * 16;
    const int nkb = (qb >> 1) + 1;

    // ---- stage Q into R0 as [64][ALD] (x0.125 exponent-only, stays tf32) ----
#pragma unroll
    for (int u = 0; u < 8; u++) {
        int i4 = u * 128 + tid;
        int r = i4 >> 4;
        int d = (i4 & 15) * 4;
        float4 v = *(const float4*)(qkv + (size_t)(q0 + r) * QKVN + h * HD + d);
        v.x *= 0.125f; v.y *= 0.125f; v.z *= 0.125f; v.w *= 0.125f;
        *(float4*)&R0[r * ALD + d] = v;
    }
    __syncthreads();

    uint32_t qf[8][4];
#pragma unroll
    for (int ks = 0; ks < 8; ks++) {
        const float* pa = R0 + (rowbase + g) * ALD + ks * 8 + t;
        qf[ks][0] = __float_as_uint(pa[0]);
        qf[ks][1] = __float_as_uint(pa[8 * ALD]);
        qf[ks][2] = __float_as_uint(pa[4]);
        qf[ks][3] = __float_as_uint(pa[8 * ALD + 4]);
    }

    float O[8][4];
    float m0 = -1e30f, m1 = -1e30f, l0 = 0.f, l1 = 0.f;
#pragma unroll
    for (int nt = 0; nt < 8; nt++)
#pragma unroll
        for (int r = 0; r < 4; r++) O[nt][r] = 0.f;

    float* PW = R0 + wid * 2048;    // warp-private P fragment buffer

    for (int kb = 0; kb < nkb; kb++) {
        __syncthreads();   // prior consumers of R0/R1 done (incl. qf reads @kb=0)

        // ---- load K -> KF (B-frag layout), V -> VF (B-frag layout) ----
#pragma unroll
        for (int u = 0; u < 16; u++) {
            int i4 = u * 128 + tid;
            int r = i4 >> 4;            // key row 0..127
            int d = (i4 & 15) * 4;      // dim 0..60 (mult of 4)
            const float* base = qkv + (size_t)(kb * 128 + r) * QKVN + h * HD;
            float4 kv = *(const float4*)(base + HID + d);
            float4 vv = *(const float4*)(base + 2 * HID + d);
            // K[r][d+j] -> KF[r>>3][ (d+j)>>3 ][ (r&7)*4 + j ][ (d>>2)&1 ]
            int koff = (r >> 3) * 528 + (d >> 3) * 66 + ((r & 7) << 3) + ((d >> 2) & 1);
            R0[koff + 0] = kv.x; R0[koff + 2] = kv.y;
            R0[koff + 4] = kv.z; R0[koff + 6] = kv.w;
            // V[r][d+j] -> VF[(d+j)>>3][ r>>3 ][ ((d&7)+j)*4 + (r&3) ][ (r>>2)&1 ]
            int voff = (d >> 3) * 1034 + (r >> 3) * 64
                     + (((d & 7) << 2) + (r & 3)) * 2 + ((r >> 2) & 1);
            R1[voff + 0]  = vv.x; R1[voff + 8]  = vv.y;
            R1[voff + 16] = vv.z; R1[voff + 24] = vv.w;
        }
        __syncthreads();

        // ---- S = Q @ K^T  (B-frag: one LDS.64 per nt per ks) ----
        float S[16][4];
#pragma unroll
        for (int nt = 0; nt < 16; nt++)
#pragma unroll
            for (int r = 0; r < 4; r++) S[nt][r] = 0.f;

#pragma unroll
        for (int ks = 0; ks < 8; ks++) {
#pragma unroll
            for (int nt = 0; nt < 16; nt++) {
                float2 b = *(const float2*)&R0[nt * 528 + ks * 66 + (lane << 1)];
                mma_tf32(S[nt], qf[ks][0], qf[ks][1], qf[ks][2], qf[ks][3],
                         __float_as_uint(b.x), __float_as_uint(b.y));
            }
        }

        // ---- causal mask (last k-block only) ----
        if (kb == nkb - 1) {
            const int r0 = q0 + rowbase + g, r1 = r0 + 8;
            const int cb = kb * 128;
#pragma unroll
            for (int nt = 0; nt < 16; nt++) {
                int c = cb + nt * 8 + 2 * t;
                if (c     > r0) S[nt][0] = -1e30f;
                if (c + 1 > r0) S[nt][1] = -1e30f;
                if (c     > r1) S[nt][2] = -1e30f;
                if (c + 1 > r1) S[nt][3] = -1e30f;
            }
        }

        // ---- online softmax ----
        float mt0 = -1e30f, mt1 = -1e30f;
#pragma unroll
        for (int nt = 0; nt < 16; nt++) {
            mt0 = fmaxf(mt0, fmaxf(S[nt][0], S[nt][1]));
            mt1 = fmaxf(mt1, fmaxf(S[nt][2], S[nt][3]));
        }
        mt0 = fmaxf(mt0, __shfl_xor_sync(0xffffffffu, mt0, 1));
        mt0 = fmaxf(mt0, __shfl_xor_sync(0xffffffffu, mt0, 2));
        mt1 = fmaxf(mt1, __shfl_xor_sync(0xffffffffu, mt1, 1));
        mt1 = fmaxf(mt1, __shfl_xor_sync(0xffffffffu, mt1, 2));
        float mn0 = fmaxf(m0, mt0), mn1 = fmaxf(m1, mt1);
        float al0 = __expf(m0 - mn0), al1 = __expf(m1 - mn1);
        float ps0 = 0.f, ps1 = 0.f;
#pragma unroll
        for (int nt = 0; nt < 16; nt++) {
            float p00 = __expf(S[nt][0] - mn0);
            float p01 = __expf(S[nt][1] - mn0);
            float p10 = __expf(S[nt][2] - mn1);
            float p11 = __expf(S[nt][3] - mn1);
            S[nt][0] = p00; S[nt][1] = p01; S[nt][2] = p10; S[nt][3] = p11;
            ps0 += p00 + p01;
            ps1 += p10 + p11;
        }
        ps0 += __shfl_xor_sync(0xffffffffu, ps0, 1);
        ps0 += __shfl_xor_sync(0xffffffffu, ps0, 2);
        ps1 += __shfl_xor_sync(0xffffffffu, ps1, 1);
        ps1 += __shfl_xor_sync(0xffffffffu, ps1, 2);
        l0 = l0 * al0 + ps0;  m0 = mn0;
        l1 = l1 * al1 + ps1;  m1 = mn1;
#pragma unroll
        for (int nt = 0; nt < 8; nt++) {
            O[nt][0] *= al0; O[nt][1] *= al0;
            O[nt][2] *= al1; O[nt][3] *= al1;
        }

        __syncthreads();   // ALL warps' KF reads done before PF overwrites R0

        // ---- stage P (tf32) into PF in A-fragment layout (warp-private) ----
        {
            const int sbase = (t < 2) ? 0 : 2;
            const int lane0 = (g << 2) + ((t & 1) << 1);
#pragma unroll
            for (int nt = 0; nt < 16; nt++) {
                float2 w0, w1;
                w0.x = tf32v(S[nt][0]); w0.y = tf32v(S[nt][2]);
                w1.x = tf32v(S[nt][1]); w1.y = tf32v(S[nt][3]);
                *(float2*)&PW[nt * 128 + lane0 * 4 + sbase]       = w0;
                *(float2*)&PW[nt * 128 + (lane0 + 1) * 4 + sbase] = w1;
            }
        }
        __syncwarp();      // PF is warp-private: warp-level ordering suffices

        // ---- O += P @ V  (A-frag: one LDS.128; B-frag: one LDS.64) ----
#pragma unroll
        for (int ks = 0; ks < 16; ks++) {
            float4 a = *(const float4*)&PW[ks * 128 + (lane << 2)];
            uint32_t a0 = __float_as_uint(a.x), a1 = __float_as_uint(a.y);
            uint32_t a2 = __float_as_uint(a.z), a3 = __float_as_uint(a.w);
#pragma unroll
            for (int nt = 0; nt < 8; nt++) {
                float2 b = *(const float2*)&R1[nt * 1034 + ks * 64 + (lane << 1)];
                mma_tf32(O[nt], a0, a1, a2, a3,
                         __float_as_uint(b.x), __float_as_uint(b.y));
            }
        }
    }

    // ---- epilogue: normalize, round to tf32 (feeds proj GEMM) ----
    float inv0 = 1.0f / l0, inv1 = 1.0f / l1;
#pragma unroll
    for (int nt = 0; nt < 8; nt++) {
        int c = h * HD + nt * 8 + 2 * t;
        float2 o0, o1;
        o0.x = tf32v(O[nt][0] * inv0); o0.y = tf32v(O[nt][1] * inv0);
        o1.x = tf32v(O[nt][2] * inv1); o1.y = tf32v(O[nt][3] * inv1);
        *(float2*)(out + (size_t)(q0 + rowbase + g)     * HID + c) = o0;
        *(float2*)(out + (size_t)(q0 + rowbase + g + 8) * HID + c) = o1;
    }
}

// ---------------------------------------------------------------------------
// Launch
// ---------------------------------------------------------------------------
extern "C" void kernel_launch(void* const* d_in, const int* in_sizes, int n_in,
                              void* d_out, int out_size)
{
    const float* x      = (const float*)d_in[0];
    const float* w_attn = (const float*)d_in[1];
    const float* b_attn = (const float*)d_in[2];
    const float* w_proj = (const float*)d_in[3];
    const float* b_proj = (const float*)d_in[4];
    float* out = (float*)d_out;

    float *qkv_p, *attn_p, *xr_p, *war_p, *wpr_p;
    cudaGetSymbolAddress((void**)&qkv_p,  g_qkv);
    cudaGetSymbolAddress((void**)&attn_p, g_attn);
    cudaGetSymbolAddress((void**)&xr_p,   g_xr);
    cudaGetSymbolAddress((void**)&war_p,  g_war);
    cudaGetSymbolAddress((void**)&wpr_p,  g_wpr);

    cudaFuncSetAttribute(attn_mma,
                         cudaFuncAttributeMaxDynamicSharedMemorySize, ATTN_BYTES);
    cudaFuncSetAttribute(gemm_tf32,
                         cudaFuncAttributeMaxDynamicSharedMemorySize, GEMM_SMEM);

    // 0) pre-round inputs to tf32 (once per call)
    round_tf32<<<(SEQ * HID / 4 + 255) / 256, 256>>>(x, xr_p, SEQ * HID / 4);
    round_tf32<<<(HID * QKVN / 4 + 255) / 256, 256>>>(w_attn, war_p, HID * QKVN / 4);
    round_tf32<<<(HID * HID / 4 + 255) / 256, 256>>>(w_proj, wpr_p, HID * HID / 4);

    // 1) QKV = Xr @ W_attn_r + b_attn     [2048, 3072]  (epilogue rounds to tf32)
    gemm_tf32<<<dim3(QKVN / 128, SEQ / 128), 256, GEMM_SMEM>>>(
        xr_p, war_p, b_attn, qkv_p, SEQ, QKVN, HID, 1);

    // 2) causal flash attention -> g_attn [2048, 1024]  (epilogue rounds to tf32)
    attn_mma<<<dim3(SEQ / 64, NH), 128, ATTN_BYTES>>>(qkv_p, attn_p);

    // 3) out = attn @ W_proj_r + b_proj   [2048, 1024]  (no rounding: final)
    gemm_tf32<<<dim3(HID / 128, SEQ / 128), 256, GEMM_SMEM>>>(
        attn_p, wpr_p, b_proj, out, SEQ, HID, HID, 0);
}

// round 10
// speedup vs baseline: 1.1731x; 1.1731x over previous
#include <cuda_runtime.h>
#include <cuda_bf16.h>
#include <cstdint>

// Problem constants
#define SEQ  2048
#define HID  1024
#define NH   16
#define HD   64
#define QKVN (3 * HID)   // 3072

// Scratch (allocation-free rule: __device__ globals)
__device__ float g_qkv[SEQ * QKVN];        // [2048, 3072]  (tf32-rounded values)
__device__ float g_attn[SEQ * HID];        // [2048, 1024]  (tf32-rounded values)
__device__ float g_xr[SEQ * HID];          // x rounded to tf32
__device__ float g_war[HID * QKVN];        // w_attn rounded to tf32
__device__ float g_wpr[HID * HID];         // w_proj rounded to tf32

// ===========================================================================
// Helpers
// ===========================================================================
__device__ __forceinline__ uint32_t smem_u32(const void* p) {
    uint32_t a;
    asm("{ .reg .u64 t; cvta.to.shared.u64 t, %1; cvt.u32.u64 %0, t; }" : "=r"(a) : "l"(p));
    return a;
}
__device__ __forceinline__ uint32_t f2tf32(float v) {
    uint32_t r;
    asm("cvt.rna.tf32.f32 %0, %1;" : "=r"(r) : "f"(v));
    return r;
}
__device__ __forceinline__ float tf32v(float v) {
    return __uint_as_float(f2tf32(v));
}
__device__ __forceinline__ void mma_tf32(float d[4],
                                         uint32_t a0, uint32_t a1, uint32_t a2, uint32_t a3,
                                         uint32_t b0, uint32_t b1) {
    asm volatile(
        "mma.sync.aligned.m16n8k8.row.col.f32.tf32.tf32.f32 "
        "{%0,%1,%2,%3}, {%4,%5,%6,%7}, {%8,%9}, {%0,%1,%2,%3};"
        : "+f"(d[0]), "+f"(d[1]), "+f"(d[2]), "+f"(d[3])
        : "r"(a0), "r"(a1), "r"(a2), "r"(a3), "r"(b0), "r"(b1));
}
#define CP_ASYNC16(dst_u32, src_ptr) \
    asm volatile("cp.async.cg.shared.global [%0], [%1], 16;" :: "r"(dst_u32), "l"(src_ptr))
#define CP_COMMIT() asm volatile("cp.async.commit_group;" ::: "memory")
#define CP_WAIT1()  asm volatile("cp.async.wait_group 1;" ::: "memory")
#define CP_WAIT0()  asm volatile("cp.async.wait_group 0;" ::: "memory")

// ===========================================================================
// Elementwise tf32 rounding pass (run once per call on x / w_attn / w_proj)
// ===========================================================================
__global__ __launch_bounds__(256) void round_tf32(
    const float* __restrict__ in, float* __restrict__ out, int n4)
{
    int i = blockIdx.x * 256 + threadIdx.x;
    if (i < n4) {
        float4 v = *(const float4*)(in + i * 4);
        float4 w;
        w.x = tf32v(v.x); w.y = tf32v(v.y); w.z = tf32v(v.z); w.w = tf32v(v.w);
        *(float4*)(out + i * 4) = w;
    }
}

// ===========================================================================
// tf32 mma.sync GEMM (R8-proven): C = A @ B + bias, B row-major.
// CTA 128x128, BK=32, 256 threads (8 warps 2x4), warp 64x32.
// 2-stage cp.async double buffer. Inputs pre-rounded to tf32.
// ===========================================================================
#define LDA 36
#define LDB 136
#define A_STAGE (128 * LDA)     // floats
#define B_STAGE (32 * LDB)
#define GEMM_SMEM ((2 * (A_STAGE + B_STAGE)) * 4)

__global__ __launch_bounds__(256)
void gemm_tf32(const float* __restrict__ A, const float* __restrict__ B,
               const float* __restrict__ bias, float* __restrict__ C,
               int M, int N, int K, int round_out)
{
    extern __shared__ float smem[];
    float* As = smem;                      // [2][A_STAGE]
    float* Bs = smem + 2 * A_STAGE;        // [2][B_STAGE]
    const uint32_t as_u32 = smem_u32(As);
    const uint32_t bs_u32 = smem_u32(Bs);

    const int tid  = threadIdx.x;
    const int wid  = tid >> 5;
    const int lane = tid & 31;
    const int g = lane >> 2;
    const int t = lane & 3;
    const int wy = wid >> 2;                // 0..1
    const int wx = wid & 3;                 // 0..3
    const int row0 = blockIdx.y * 128;
    const int col0 = blockIdx.x * 128;
    const int NS = K >> 5;

    const float* Ag = A + (size_t)row0 * K;
    const float* Bg = B + col0;

    auto copy_stage = [&](int s, int buf) {
        const int k0 = s * 32;
#pragma unroll
        for (int u = 0; u < 4; u++) {
            int idx = u * 256 + tid;
            int row = idx >> 3;
            int c4  = idx & 7;
            CP_ASYNC16(as_u32 + (buf * A_STAGE + row * LDA + c4 * 4) * 4,
                       Ag + (size_t)row * K + k0 + c4 * 4);
        }
#pragma unroll
        for (int u = 0; u < 4; u++) {
            int idx = u * 256 + tid;
            int row = idx >> 5;
            int c4  = idx & 31;
            CP_ASYNC16(bs_u32 + (buf * B_STAGE + row * LDB + c4 * 4) * 4,
                       Bg + (size_t)(k0 + row) * N + c4 * 4);
        }
    };

    float acc[4][4][4];
#pragma unroll
    for (int mt = 0; mt < 4; mt++)
#pragma unroll
        for (int nt = 0; nt < 4; nt++)
#pragma unroll
            for (int r = 0; r < 4; r++) acc[mt][nt][r] = 0.f;

    copy_stage(0, 0);
    CP_COMMIT();

    for (int s = 0; s < NS; s++) {
        const int buf = s & 1;
        if (s + 1 < NS) {
            copy_stage(s + 1, buf ^ 1);
            CP_COMMIT();
            CP_WAIT1();
        } else {
            CP_WAIT0();
        }
        __syncthreads();

        const float* Ab = As + buf * A_STAGE;
        const float* Bb = Bs + buf * B_STAGE;

#pragma unroll
        for (int ks = 0; ks < 4; ks++) {
            const int kk = ks * 8;
            uint32_t af[4][4];
#pragma unroll
            for (int mt = 0; mt < 4; mt++) {
                const float* pa = Ab + (wy * 64 + mt * 16 + g) * LDA + kk + t;
                af[mt][0] = __float_as_uint(pa[0]);
                af[mt][1] = __float_as_uint(pa[8 * LDA]);
                af[mt][2] = __float_as_uint(pa[4]);
                af[mt][3] = __float_as_uint(pa[8 * LDA + 4]);
            }
            uint32_t bf[4][2];
#pragma unroll
            for (int nt = 0; nt < 4; nt++) {
                const float* pb = Bb + (kk + t) * LDB + wx * 32 + nt * 8 + g;
                bf[nt][0] = __float_as_uint(pb[0]);
                bf[nt][1] = __float_as_uint(pb[4 * LDB]);
            }
#pragma unroll
            for (int mt = 0; mt < 4; mt++)
#pragma unroll
                for (int nt = 0; nt < 4; nt++)
                    mma_tf32(acc[mt][nt], af[mt][0], af[mt][1], af[mt][2], af[mt][3],
                             bf[nt][0], bf[nt][1]);
        }
        __syncthreads();
    }

#pragma unroll
    for (int mt = 0; mt < 4; mt++) {
        int m = row0 + wy * 64 + mt * 16 + g;
#pragma unroll
        for (int nt = 0; nt < 4; nt++) {
            int n = col0 + wx * 32 + nt * 8 + 2 * t;
            float2 o0, o1;
            o0.x = acc[mt][nt][0] + bias[n];
            o0.y = acc[mt][nt][1] + bias[n + 1];
            o1.x = acc[mt][nt][2] + bias[n];
            o1.y = acc[mt][nt][3] + bias[n + 1];
            if (round_out) {
                o0.x = tf32v(o0.x); o0.y = tf32v(o0.y);
                o1.x = tf32v(o1.x); o1.y = tf32v(o1.y);
            }
            *(float2*)(C + (size_t)m * N + n)       = o0;
            *(float2*)(C + (size_t)(m + 8) * N + n) = o1;
        }
    }
}

// ===========================================================================
// Flash attention, tf32 mma.sync. CTA = (head, 64 q rows), 4 warps.
// R8 row-major K/V smem (vectorized writes, conflict-free reads).
// NEW vs R8: P·V A-fragments built by in-register shfl transpose of S
// (no P smem round-trip, 2 fewer syncthreads/block), K/V loads via cp.async.
// ===========================================================================
#define ALD 68                       // K lead dim (S-phase B reads: bank 4g+t)
#define VLD 72                       // V lead dim (PV B reads: bank 8t+g)
#define KP_FLOATS (128 * ALD)        // K tile (also Q staging area before loop)
#define AT_V  KP_FLOATS
#define ATTN_FLOATS (KP_FLOATS + 128 * VLD)
#define ATTN_BYTES  (ATTN_FLOATS * 4)

__global__ __launch_bounds__(128)
void attn_mma(const float* __restrict__ qkv, float* __restrict__ out)
{
    extern __shared__ float sm[];
    float* KPs = sm;               // K tile (Q staged here once before loop)
    float* Vs  = sm + AT_V;
    const uint32_t kp_u32 = smem_u32(KPs);
    const uint32_t vs_u32 = smem_u32(Vs);

    const int tid  = threadIdx.x;
    const int lane = tid & 31;
    const int wid  = tid >> 5;     // 0..3
    const int g = lane >> 2;
    const int t = lane & 3;
    const int h  = blockIdx.y;
    const int qb = (int)gridDim.x - 1 - (int)blockIdx.x;   // heavy CTAs first
    const int q0 = qb * 64;
    const int rowbase = wid * 16;
    const int nkb = (qb >> 1) + 1;

    // ---- stage Q into KPs (x0.125 exponent-only: stays valid tf32) ----
#pragma unroll
    for (int u = 0; u < 8; u++) {
        int i4 = u * 128 + tid;
        int r = i4 >> 4;
        int d = (i4 & 15) * 4;
        float4 v = *(const float4*)(qkv + (size_t)(q0 + r) * QKVN + h * HD + d);
        v.x *= 0.125f; v.y *= 0.125f; v.z *= 0.125f; v.w *= 0.125f;
        *(float4*)&KPs[r * ALD + d] = v;
    }
    __syncthreads();

    uint32_t qf[8][4];
#pragma unroll
    for (int ks = 0; ks < 8; ks++) {
        const float* pa = KPs + (rowbase + g) * ALD + ks * 8 + t;
        qf[ks][0] = __float_as_uint(pa[0]);
        qf[ks][1] = __float_as_uint(pa[8 * ALD]);
        qf[ks][2] = __float_as_uint(pa[4]);
        qf[ks][3] = __float_as_uint(pa[8 * ALD + 4]);
    }

    float O[8][4];
    float m0 = -1e30f, m1 = -1e30f, l0 = 0.f, l1 = 0.f;
#pragma unroll
    for (int nt = 0; nt < 8; nt++)
#pragma unroll
        for (int r = 0; r < 4; r++) O[nt][r] = 0.f;

    for (int kb = 0; kb < nkb; kb++) {
        __syncthreads();   // prior consumers of KPs/Vs done (incl. qf reads @kb=0)

        // ---- async copy K -> KPs, V -> Vs (values already tf32) ----
#pragma unroll
        for (int u = 0; u < 16; u++) {
            int i4 = u * 128 + tid;
            int r = i4 >> 4;
            int d = (i4 & 15) * 4;
            const float* base = qkv + (size_t)(kb * 128 + r) * QKVN + h * HD;
            CP_ASYNC16(kp_u32 + (r * ALD + d) * 4, base + HID + d);
            CP_ASYNC16(vs_u32 + (r * VLD + d) * 4, base + 2 * HID + d);
        }
        CP_COMMIT();
        CP_WAIT0();
        __syncthreads();

        // ---- S = Q @ K^T ----
        float S[16][4];
#pragma unroll
        for (int nt = 0; nt < 16; nt++)
#pragma unroll
            for (int r = 0; r < 4; r++) S[nt][r] = 0.f;

#pragma unroll
        for (int ks = 0; ks < 8; ks++) {
#pragma unroll
            for (int nt = 0; nt < 16; nt++) {
                const float* pb = KPs + (nt * 8 + g) * ALD + ks * 8 + t;
                uint32_t b0 = __float_as_uint(pb[0]);
                uint32_t b1 = __float_as_uint(pb[4]);
                mma_tf32(S[nt], qf[ks][0], qf[ks][1], qf[ks][2], qf[ks][3], b0, b1);
            }
        }

        // ---- causal mask (last k-block only) ----
        if (kb == nkb - 1) {
            const int r0 = q0 + rowbase + g, r1 = r0 + 8;
            const int cb = kb * 128;
#pragma unroll
            for (int nt = 0; nt < 16; nt++) {
                int c = cb + nt * 8 + 2 * t;
                if (c     > r0) S[nt][0] = -1e30f;
                if (c + 1 > r0) S[nt][1] = -1e30f;
                if (c     > r1) S[nt][2] = -1e30f;
                if (c + 1 > r1) S[nt][3] = -1e30f;
            }
        }

        // ---- online softmax ----
        float mt0 = -1e30f, mt1 = -1e30f;
#pragma unroll
        for (int nt = 0; nt < 16; nt++) {
            mt0 = fmaxf(mt0, fmaxf(S[nt][0], S[nt][1]));
            mt1 = fmaxf(mt1, fmaxf(S[nt][2], S[nt][3]));
        }
        mt0 = fmaxf(mt0, __shfl_xor_sync(0xffffffffu, mt0, 1));
        mt0 = fmaxf(mt0, __shfl_xor_sync(0xffffffffu, mt0, 2));
        mt1 = fmaxf(mt1, __shfl_xor_sync(0xffffffffu, mt1, 1));
        mt1 = fmaxf(mt1, __shfl_xor_sync(0xffffffffu, mt1, 2));
        float mn0 = fmaxf(m0, mt0), mn1 = fmaxf(m1, mt1);
        float al0 = __expf(m0 - mn0), al1 = __expf(m1 - mn1);
        float ps0 = 0.f, ps1 = 0.f;
#pragma unroll
        for (int nt = 0; nt < 16; nt++) {
            float p00 = __expf(S[nt][0] - mn0);
            float p01 = __expf(S[nt][1] - mn0);
            float p10 = __expf(S[nt][2] - mn1);
            float p11 = __expf(S[nt][3] - mn1);
            S[nt][0] = p00; S[nt][1] = p01; S[nt][2] = p10; S[nt][3] = p11;
            ps0 += p00 + p01;
            ps1 += p10 + p11;
        }
        ps0 += __shfl_xor_sync(0xffffffffu, ps0, 1);
        ps0 += __shfl_xor_sync(0xffffffffu, ps0, 2);
        ps1 += __shfl_xor_sync(0xffffffffu, ps1, 1);
        ps1 += __shfl_xor_sync(0xffffffffu, ps1, 2);
        l0 = l0 * al0 + ps0;  m0 = mn0;
        l1 = l1 * al1 + ps1;  m1 = mn1;
#pragma unroll
        for (int nt = 0; nt < 8; nt++) {
            O[nt][0] *= al0; O[nt][1] *= al0;
            O[nt][2] *= al1; O[nt][3] *= al1;
        }

        // ---- O += P @ V : A-frag via shfl transpose of S (no smem, no sync) ----
        // a0 = P[g][8ks+t] lives in quad lane 4g+(t>>1), slot t&1 (row g: slots 0/1,
        // row g+8: slots 2/3); a2/a3 (cols t+4) in lane 4g+2+(t>>1).
        {
            const int src0 = (lane & 28) | (t >> 1);
            const int src1 = src0 | 2;
            const bool odd = (t & 1);
#pragma unroll
            for (int ks = 0; ks < 16; ks++) {
                float p0 = tf32v(S[ks][0]), p1 = tf32v(S[ks][1]);
                float p2 = tf32v(S[ks][2]), p3 = tf32v(S[ks][3]);
                float v00 = __shfl_sync(0xffffffffu, p0, src0);
                float v01 = __shfl_sync(0xffffffffu, p1, src0);
                float v02 = __shfl_sync(0xffffffffu, p2, src0);
                float v03 = __shfl_sync(0xffffffffu, p3, src0);
                float v10 = __shfl_sync(0xffffffffu, p0, src1);
                float v11 = __shfl_sync(0xffffffffu, p1, src1);
                float v12 = __shfl_sync(0xffffffffu, p2, src1);
                float v13 = __shfl_sync(0xffffffffu, p3, src1);
                uint32_t a0 = __float_as_uint(odd ? v01 : v00);
                uint32_t a1 = __float_as_uint(odd ? v03 : v02);
                uint32_t a2 = __float_as_uint(odd ? v11 : v10);
                uint32_t a3 = __float_as_uint(odd ? v13 : v12);
#pragma unroll
                for (int nt = 0; nt < 8; nt++) {
                    uint32_t b0 = __float_as_uint(Vs[(ks * 8 + t)     * VLD + nt * 8 + g]);
                    uint32_t b1 = __float_as_uint(Vs[(ks * 8 + t + 4) * VLD + nt * 8 + g]);
                    mma_tf32(O[nt], a0, a1, a2, a3, b0, b1);
                }
            }
        }
    }

    // ---- epilogue: normalize, round to tf32 (feeds proj GEMM) ----
    float inv0 = 1.0f / l0, inv1 = 1.0f / l1;
#pragma unroll
    for (int nt = 0; nt < 8; nt++) {
        int c = h * HD + nt * 8 + 2 * t;
        float2 o0, o1;
        o0.x = tf32v(O[nt][0] * inv0); o0.y = tf32v(O[nt][1] * inv0);
        o1.x = tf32v(O[nt][2] * inv1); o1.y = tf32v(O[nt][3] * inv1);
        *(float2*)(out + (size_t)(q0 + rowbase + g)     * HID + c) = o0;
        *(float2*)(out + (size_t)(q0 + rowbase + g + 8) * HID + c) = o1;
    }
}

// ---------------------------------------------------------------------------
// Launch
// ---------------------------------------------------------------------------
extern "C" void kernel_launch(void* const* d_in, const int* in_sizes, int n_in,
                              void* d_out, int out_size)
{
    const float* x      = (const float*)d_in[0];
    const float* w_attn = (const float*)d_in[1];
    const float* b_attn = (const float*)d_in[2];
    const float* w_proj = (const float*)d_in[3];
    const float* b_proj = (const float*)d_in[4];
    float* out = (float*)d_out;

    float *qkv_p, *attn_p, *xr_p, *war_p, *wpr_p;
    cudaGetSymbolAddress((void**)&qkv_p,  g_qkv);
    cudaGetSymbolAddress((void**)&attn_p, g_attn);
    cudaGetSymbolAddress((void**)&xr_p,   g_xr);
    cudaGetSymbolAddress((void**)&war_p,  g_war);
    cudaGetSymbolAddress((void**)&wpr_p,  g_wpr);

    cudaFuncSetAttribute(attn_mma,
                         cudaFuncAttributeMaxDynamicSharedMemorySize, ATTN_BYTES);
    cudaFuncSetAttribute(gemm_tf32,
                         cudaFuncAttributeMaxDynamicSharedMemorySize, GEMM_SMEM);

    // 0) pre-round inputs to tf32 (once per call)
    round_tf32<<<(SEQ * HID / 4 + 255) / 256, 256>>>(x, xr_p, SEQ * HID / 4);
    round_tf32<<<(HID * QKVN / 4 + 255) / 256, 256>>>(w_attn, war_p, HID * QKVN / 4);
    round_tf32<<<(HID * HID / 4 + 255) / 256, 256>>>(w_proj, wpr_p, HID * HID / 4);

    // 1) QKV = Xr @ W_attn_r + b_attn     [2048, 3072]  (epilogue rounds to tf32)
    gemm_tf32<<<dim3(QKVN / 128, SEQ / 128), 256, GEMM_SMEM>>>(
        xr_p, war_p, b_attn, qkv_p, SEQ, QKVN, HID, 1);

    // 2) causal flash attention -> g_attn [2048, 1024]  (epilogue rounds to tf32)
    attn_mma<<<dim3(SEQ / 64, NH), 128, ATTN_BYTES>>>(qkv_p, attn_p);

    // 3) out = attn @ W_proj_r + b_proj   [2048, 1024]  (no rounding: final)
    gemm_tf32<<<dim3(HID / 128, SEQ / 128), 256, GEMM_SMEM>>>(
        attn_p, wpr_p, b_proj, out, SEQ, HID, HID, 0);
}

// round 12
// speedup vs baseline: 1.2134x; 1.0344x over previous
#include <cuda_runtime.h>
#include <cuda_bf16.h>
#include <cstdint>

// Problem constants
#define SEQ  2048
#define HID  1024
#define NH   16
#define HD   64
#define QKVN (3 * HID)   // 3072

// Scratch (allocation-free rule: __device__ globals)
__device__ float g_qkv[SEQ * QKVN];        // [2048, 3072]  (tf32-rounded values)
__device__ float g_attn[SEQ * HID];        // [2048, 1024]  (tf32-rounded values)
__device__ float g_xr[SEQ * HID];          // x rounded to tf32
__device__ float g_war[HID * QKVN];        // w_attn rounded to tf32
__device__ float g_wpr[HID * HID];         // w_proj rounded to tf32

// ===========================================================================
// Helpers
// ===========================================================================
__device__ __forceinline__ uint32_t smem_u32(const void* p) {
    uint32_t a;
    asm("{ .reg .u64 t; cvta.to.shared.u64 t, %1; cvt.u32.u64 %0, t; }" : "=r"(a) : "l"(p));
    return a;
}
__device__ __forceinline__ uint32_t f2tf32(float v) {
    uint32_t r;
    asm("cvt.rna.tf32.f32 %0, %1;" : "=r"(r) : "f"(v));
    return r;
}
__device__ __forceinline__ float tf32v(float v) {
    return __uint_as_float(f2tf32(v));
}
__device__ __forceinline__ void mma_tf32(float d[4],
                                         uint32_t a0, uint32_t a1, uint32_t a2, uint32_t a3,
                                         uint32_t b0, uint32_t b1) {
    asm volatile(
        "mma.sync.aligned.m16n8k8.row.col.f32.tf32.tf32.f32 "
        "{%0,%1,%2,%3}, {%4,%5,%6,%7}, {%8,%9}, {%0,%1,%2,%3};"
        : "+f"(d[0]), "+f"(d[1]), "+f"(d[2]), "+f"(d[3])
        : "r"(a0), "r"(a1), "r"(a2), "r"(a3), "r"(b0), "r"(b1));
}
#define CP_ASYNC16(dst_u32, src_ptr) \
    asm volatile("cp.async.cg.shared.global [%0], [%1], 16;" :: "r"(dst_u32), "l"(src_ptr))
#define CP_COMMIT() asm volatile("cp.async.commit_group;" ::: "memory")
#define CP_WAIT1()  asm volatile("cp.async.wait_group 1;" ::: "memory")
#define CP_WAIT0()  asm volatile("cp.async.wait_group 0;" ::: "memory")

// ===========================================================================
// Fused elementwise tf32 rounding for x / w_attn / w_proj (one launch)
// ===========================================================================
#define XR_N4  (SEQ * HID / 4)
#define WAR_N4 (HID * QKVN / 4)
#define WPR_N4 (HID * HID / 4)
#define ROUND_TOTAL4 (XR_N4 + WAR_N4 + WPR_N4)

__global__ __launch_bounds__(256) void round3_tf32(
    const float* __restrict__ a, float* __restrict__ ar,
    const float* __restrict__ b, float* __restrict__ br,
    const float* __restrict__ c, float* __restrict__ cr)
{
    int i = blockIdx.x * 256 + threadIdx.x;
    const float* src; float* dst; int idx;
    if (i < XR_N4)                 { src = a; dst = ar; idx = i; }
    else if (i < XR_N4 + WAR_N4)   { src = b; dst = br; idx = i - XR_N4; }
    else if (i < ROUND_TOTAL4)     { src = c; dst = cr; idx = i - XR_N4 - WAR_N4; }
    else return;
    float4 v = *(const float4*)(src + (size_t)idx * 4);
    float4 w;
    w.x = tf32v(v.x); w.y = tf32v(v.y); w.z = tf32v(v.z); w.w = tf32v(v.w);
    *(float4*)(dst + (size_t)idx * 4) = w;
}

// ===========================================================================
// tf32 mma.sync GEMM: C[M,N] = A[M,K] @ B[K,N] + bias[N]   (B row-major)
// NEW shape: CTA tile 64x128, 128 threads (4 warps 2x2), warp tile 32x64.
// 4 CTAs/SM (53KB smem, 128-reg cap) -> smaller wave quantization + more
// warps to hide LDS->MMA latency. 2-stage cp.async (proven control flow).
// Per-output accumulation order identical to R8/R10 -> bit-identical result.
// ===========================================================================
#define LDA 36
#define LDB 136
#define A_STAGE (64 * LDA)      // floats
#define B_STAGE (32 * LDB)
#define GEMM_SMEM ((2 * (A_STAGE + B_STAGE)) * 4)

__global__ __launch_bounds__(128, 4)
void gemm_tf32(const float* __restrict__ A, const float* __restrict__ B,
               const float* __restrict__ bias, float* __restrict__ C,
               int M, int N, int K, int round_out)
{
    extern __shared__ float smem[];
    float* As = smem;                      // [2][A_STAGE]
    float* Bs = smem + 2 * A_STAGE;        // [2][B_STAGE]
    const uint32_t as_u32 = smem_u32(As);
    const uint32_t bs_u32 = smem_u32(Bs);

    const int tid  = threadIdx.x;
    const int wid  = tid >> 5;
    const int lane = tid & 31;
    const int g = lane >> 2;
    const int t = lane & 3;
    const int wy = wid >> 1;                // 0..1 (M)
    const int wx = wid & 1;                 // 0..1 (N)
    const int row0 = blockIdx.y * 64;
    const int col0 = blockIdx.x * 128;
    const int NS = K >> 5;

    const float* Ag = A + (size_t)row0 * K;
    const float* Bg = B + col0;

    auto copy_stage = [&](int s, int buf) {
        const int k0 = s * 32;
        // A: 64 rows x 8 float4 = 512 -> 4 per thread
#pragma unroll
        for (int u = 0; u < 4; u++) {
            int idx = u * 128 + tid;
            int row = idx >> 3;
            int c4  = idx & 7;
            CP_ASYNC16(as_u32 + (buf * A_STAGE + row * LDA + c4 * 4) * 4,
                       Ag + (size_t)row * K + k0 + c4 * 4);
        }
        // B: 32 rows x 32 float4 = 1024 -> 8 per thread
#pragma unroll
        for (int u = 0; u < 8; u++) {
            int idx = u * 128 + tid;
            int row = idx >> 5;
            int c4  = idx & 31;
            CP_ASYNC16(bs_u32 + (buf * B_STAGE + row * LDB + c4 * 4) * 4,
                       Bg + (size_t)(k0 + row) * N + c4 * 4);
        }
    };

    float acc[2][8][4];
#pragma unroll
    for (int mt = 0; mt < 2; mt++)
#pragma unroll
        for (int nt = 0; nt < 8; nt++)
#pragma unroll
            for (int r = 0; r < 4; r++) acc[mt][nt][r] = 0.f;

    copy_stage(0, 0);
    CP_COMMIT();

    for (int s = 0; s < NS; s++) {
        const int buf = s & 1;
        if (s + 1 < NS) {
            copy_stage(s + 1, buf ^ 1);
            CP_COMMIT();
            CP_WAIT1();
        } else {
            CP_WAIT0();
        }
        __syncthreads();

        const float* Ab = As + buf * A_STAGE;
        const float* Bb = Bs + buf * B_STAGE;

#pragma unroll
        for (int ks = 0; ks < 4; ks++) {
            const int kk = ks * 8;
            uint32_t af[2][4];
#pragma unroll
            for (int mt = 0; mt < 2; mt++) {
                const float* pa = Ab + (wy * 32 + mt * 16 + g) * LDA + kk + t;
                af[mt][0] = __float_as_uint(pa[0]);
                af[mt][1] = __float_as_uint(pa[8 * LDA]);
                af[mt][2] = __float_as_uint(pa[4]);
                af[mt][3] = __float_as_uint(pa[8 * LDA + 4]);
            }
            uint32_t bf[8][2];
#pragma unroll
            for (int nt = 0; nt < 8; nt++) {
                const float* pb = Bb + (kk + t) * LDB + wx * 64 + nt * 8 + g;
                bf[nt][0] = __float_as_uint(pb[0]);
                bf[nt][1] = __float_as_uint(pb[4 * LDB]);
            }
#pragma unroll
            for (int mt = 0; mt < 2; mt++)
#pragma unroll
                for (int nt = 0; nt < 8; nt++)
                    mma_tf32(acc[mt][nt], af[mt][0], af[mt][1], af[mt][2], af[mt][3],
                             bf[nt][0], bf[nt][1]);
        }
        __syncthreads();
    }

#pragma unroll
    for (int mt = 0; mt < 2; mt++) {
        int m = row0 + wy * 32 + mt * 16 + g;
#pragma unroll
        for (int nt = 0; nt < 8; nt++) {
            int n = col0 + wx * 64 + nt * 8 + 2 * t;
            float2 o0, o1;
            o0.x = acc[mt][nt][0] + bias[n];
            o0.y = acc[mt][nt][1] + bias[n + 1];
            o1.x = acc[mt][nt][2] + bias[n];
            o1.y = acc[mt][nt][3] + bias[n + 1];
            if (round_out) {
                o0.x = tf32v(o0.x); o0.y = tf32v(o0.y);
                o1.x = tf32v(o1.x); o1.y = tf32v(o1.y);
            }
            *(float2*)(C + (size_t)m * N + n)       = o0;
            *(float2*)(C + (size_t)(m + 8) * N + n) = o1;
        }
    }
}

// ===========================================================================
// Flash attention, tf32 mma.sync (unchanged from R10 — proven).
// CTA = (head, 64 q rows), 4 warps. Q persistent fragments, shfl-transposed
// P (no P smem round-trip), cp.async K/V loads.
// ===========================================================================
#define ALD 68                       // K lead dim (S-phase B reads: bank 4g+t)
#define VLD 72                       // V lead dim (PV B reads: bank 8t+g)
#define KP_FLOATS (128 * ALD)        // K tile (also Q staging area before loop)
#define AT_V  KP_FLOATS
#define ATTN_FLOATS (KP_FLOATS + 128 * VLD)
#define ATTN_BYTES  (ATTN_FLOATS * 4)

__global__ __launch_bounds__(128)
void attn_mma(const float* __restrict__ qkv, float* __restrict__ out)
{
    extern __shared__ float sm[];
    float* KPs = sm;               // K tile (Q staged here once before loop)
    float* Vs  = sm + AT_V;
    const uint32_t kp_u32 = smem_u32(KPs);
    const uint32_t vs_u32 = smem_u32(Vs);

    const int tid  = threadIdx.x;
    const int lane = tid & 31;
    const int wid  = tid >> 5;     // 0..3
    const int g = lane >> 2;
    const int t = lane & 3;
    const int h  = blockIdx.y;
    const int qb = (int)gridDim.x - 1 - (int)blockIdx.x;   // heavy CTAs first
    const int q0 = qb * 64;
    const int rowbase = wid * 16;
    const int nkb = (qb >> 1) + 1;

    // ---- stage Q into KPs (x0.125 exponent-only: stays valid tf32) ----
#pragma unroll
    for (int u = 0; u < 8; u++) {
        int i4 = u * 128 + tid;
        int r = i4 >> 4;
        int d = (i4 & 15) * 4;
        float4 v = *(const float4*)(qkv + (size_t)(q0 + r) * QKVN + h * HD + d);
        v.x *= 0.125f; v.y *= 0.125f; v.z *= 0.125f; v.w *= 0.125f;
        *(float4*)&KPs[r * ALD + d] = v;
    }
    __syncthreads();

    uint32_t qf[8][4];
#pragma unroll
    for (int ks = 0; ks < 8; ks++) {
        const float* pa = KPs + (rowbase + g) * ALD + ks * 8 + t;
        qf[ks][0] = __float_as_uint(pa[0]);
        qf[ks][1] = __float_as_uint(pa[8 * ALD]);
        qf[ks][2] = __float_as_uint(pa[4]);
        qf[ks][3] = __float_as_uint(pa[8 * ALD + 4]);
    }

    float O[8][4];
    float m0 = -1e30f, m1 = -1e30f, l0 = 0.f, l1 = 0.f;
#pragma unroll
    for (int nt = 0; nt < 8; nt++)
#pragma unroll
        for (int r = 0; r < 4; r++) O[nt][r] = 0.f;

    for (int kb = 0; kb < nkb; kb++) {
        __syncthreads();   // prior consumers of KPs/Vs done (incl. qf reads @kb=0)

        // ---- async copy K -> KPs, V -> Vs (values already tf32) ----
#pragma unroll
        for (int u = 0; u < 16; u++) {
            int i4 = u * 128 + tid;
            int r = i4 >> 4;
            int d = (i4 & 15) * 4;
            const float* base = qkv + (size_t)(kb * 128 + r) * QKVN + h * HD;
            CP_ASYNC16(kp_u32 + (r * ALD + d) * 4, base + HID + d);
            CP_ASYNC16(vs_u32 + (r * VLD + d) * 4, base + 2 * HID + d);
        }
        CP_COMMIT();
        CP_WAIT0();
        __syncthreads();

        // ---- S = Q @ K^T ----
        float S[16][4];
#pragma unroll
        for (int nt = 0; nt < 16; nt++)
#pragma unroll
            for (int r = 0; r < 4; r++) S[nt][r] = 0.f;

#pragma unroll
        for (int ks = 0; ks < 8; ks++) {
#pragma unroll
            for (int nt = 0; nt < 16; nt++) {
                const float* pb = KPs + (nt * 8 + g) * ALD + ks * 8 + t;
                uint32_t b0 = __float_as_uint(pb[0]);
                uint32_t b1 = __float_as_uint(pb[4]);
                mma_tf32(S[nt], qf[ks][0], qf[ks][1], qf[ks][2], qf[ks][3], b0, b1);
            }
        }

        // ---- causal mask (last k-block only) ----
        if (kb == nkb - 1) {
            const int r0 = q0 + rowbase + g, r1 = r0 + 8;
            const int cb = kb * 128;
#pragma unroll
            for (int nt = 0; nt < 16; nt++) {
                int c = cb + nt * 8 + 2 * t;
                if (c     > r0) S[nt][0] = -1e30f;
                if (c + 1 > r0) S[nt][1] = -1e30f;
                if (c     > r1) S[nt][2] = -1e30f;
                if (c + 1 > r1) S[nt][3] = -1e30f;
            }
        }

        // ---- online softmax ----
        float mt0 = -1e30f, mt1 = -1e30f;
#pragma unroll
        for (int nt = 0; nt < 16; nt++) {
            mt0 = fmaxf(mt0, fmaxf(S[nt][0], S[nt][1]));
            mt1 = fmaxf(mt1, fmaxf(S[nt][2], S[nt][3]));
        }
        mt0 = fmaxf(mt0, __shfl_xor_sync(0xffffffffu, mt0, 1));
        mt0 = fmaxf(mt0, __shfl_xor_sync(0xffffffffu, mt0, 2));
        mt1 = fmaxf(mt1, __shfl_xor_sync(0xffffffffu, mt1, 1));
        mt1 = fmaxf(mt1, __shfl_xor_sync(0xffffffffu, mt1, 2));
        float mn0 = fmaxf(m0, mt0), mn1 = fmaxf(m1, mt1);
        float al0 = __expf(m0 - mn0), al1 = __expf(m1 - mn1);
        float ps0 = 0.f, ps1 = 0.f;
#pragma unroll
        for (int nt = 0; nt < 16; nt++) {
            float p00 = __expf(S[nt][0] - mn0);
            float p01 = __expf(S[nt][1] - mn0);
            float p10 = __expf(S[nt][2] - mn1);
            float p11 = __expf(S[nt][3] - mn1);
            S[nt][0] = p00; S[nt][1] = p01; S[nt][2] = p10; S[nt][3] = p11;
            ps0 += p00 + p01;
            ps1 += p10 + p11;
        }
        ps0 += __shfl_xor_sync(0xffffffffu, ps0, 1);
        ps0 += __shfl_xor_sync(0xffffffffu, ps0, 2);
        ps1 += __shfl_xor_sync(0xffffffffu, ps1, 1);
        ps1 += __shfl_xor_sync(0xffffffffu, ps1, 2);
        l0 = l0 * al0 + ps0;  m0 = mn0;
        l1 = l1 * al1 + ps1;  m1 = mn1;
#pragma unroll
        for (int nt = 0; nt < 8; nt++) {
            O[nt][0] *= al0; O[nt][1] *= al0;
            O[nt][2] *= al1; O[nt][3] *= al1;
        }

        // ---- O += P @ V : A-frag via shfl transpose of S (no smem, no sync) ----
        {
            const int src0 = (lane & 28) | (t >> 1);
            const int src1 = src0 | 2;
            const bool odd = (t & 1);
#pragma unroll
            for (int ks = 0; ks < 16; ks++) {
                float p0 = tf32v(S[ks][0]), p1 = tf32v(S[ks][1]);
                float p2 = tf32v(S[ks][2]), p3 = tf32v(S[ks][3]);
                float v00 = __shfl_sync(0xffffffffu, p0, src0);
                float v01 = __shfl_sync(0xffffffffu, p1, src0);
                float v02 = __shfl_sync(0xffffffffu, p2, src0);
                float v03 = __shfl_sync(0xffffffffu, p3, src0);
                float v10 = __shfl_sync(0xffffffffu, p0, src1);
                float v11 = __shfl_sync(0xffffffffu, p1, src1);
                float v12 = __shfl_sync(0xffffffffu, p2, src1);
                float v13 = __shfl_sync(0xffffffffu, p3, src1);
                uint32_t a0 = __float_as_uint(odd ? v01 : v00);
                uint32_t a1 = __float_as_uint(odd ? v03 : v02);
                uint32_t a2 = __float_as_uint(odd ? v11 : v10);
                uint32_t a3 = __float_as_uint(odd ? v13 : v12);
#pragma unroll
                for (int nt = 0; nt < 8; nt++) {
                    uint32_t b0 = __float_as_uint(Vs[(ks * 8 + t)     * VLD + nt * 8 + g]);
                    uint32_t b1 = __float_as_uint(Vs[(ks * 8 + t + 4) * VLD + nt * 8 + g]);
                    mma_tf32(O[nt], a0, a1, a2, a3, b0, b1);
                }
            }
        }
    }

    // ---- epilogue: normalize, round to tf32 (feeds proj GEMM) ----
    float inv0 = 1.0f / l0, inv1 = 1.0f / l1;
#pragma unroll
    for (int nt = 0; nt < 8; nt++) {
        int c = h * HD + nt * 8 + 2 * t;
        float2 o0, o1;
        o0.x = tf32v(O[nt][0] * inv0); o0.y = tf32v(O[nt][1] * inv0);
        o1.x = tf32v(O[nt][2] * inv1); o1.y = tf32v(O[nt][3] * inv1);
        *(float2*)(out + (size_t)(q0 + rowbase + g)     * HID + c) = o0;
        *(float2*)(out + (size_t)(q0 + rowbase + g + 8) * HID + c) = o1;
    }
}

// ---------------------------------------------------------------------------
// Launch
// ---------------------------------------------------------------------------
extern "C" void kernel_launch(void* const* d_in, const int* in_sizes, int n_in,
                              void* d_out, int out_size)
{
    const float* x      = (const float*)d_in[0];
    const float* w_attn = (const float*)d_in[1];
    const float* b_attn = (const float*)d_in[2];
    const float* w_proj = (const float*)d_in[3];
    const float* b_proj = (const float*)d_in[4];
    float* out = (float*)d_out;

    float *qkv_p, *attn_p, *xr_p, *war_p, *wpr_p;
    cudaGetSymbolAddress((void**)&qkv_p,  g_qkv);
    cudaGetSymbolAddress((void**)&attn_p, g_attn);
    cudaGetSymbolAddress((void**)&xr_p,   g_xr);
    cudaGetSymbolAddress((void**)&war_p,  g_war);
    cudaGetSymbolAddress((void**)&wpr_p,  g_wpr);

    cudaFuncSetAttribute(attn_mma,
                         cudaFuncAttributeMaxDynamicSharedMemorySize, ATTN_BYTES);
    cudaFuncSetAttribute(gemm_tf32,
                         cudaFuncAttributeMaxDynamicSharedMemorySize, GEMM_SMEM);

    // 0) pre-round inputs to tf32 (single fused launch)
    round3_tf32<<<(ROUND_TOTAL4 + 255) / 256, 256>>>(
        x, xr_p, w_attn, war_p, w_proj, wpr_p);

    // 1) QKV = Xr @ W_attn_r + b_attn     [2048, 3072]  (epilogue rounds to tf32)
    gemm_tf32<<<dim3(QKVN / 128, SEQ / 64), 128, GEMM_SMEM>>>(
        xr_p, war_p, b_attn, qkv_p, SEQ, QKVN, HID, 1);

    // 2) causal flash attention -> g_attn [2048, 1024]  (epilogue rounds to tf32)
    attn_mma<<<dim3(SEQ / 64, NH), 128, ATTN_BYTES>>>(qkv_p, attn_p);

    // 3) out = attn @ W_proj_r + b_proj   [2048, 1024]  (no rounding: final)
    gemm_tf32<<<dim3(HID / 128, SEQ / 64), 128, GEMM_SMEM>>>(
        attn_p, wpr_p, b_proj, out, SEQ, HID, HID, 0);
}